// round 2
// baseline (speedup 1.0000x reference)
#include <cuda_runtime.h>
#include <cuda_bf16.h>
#include <math.h>

#define NN 100000
#define EE 1600000
#define DIM 128
#define HEADS 4
#define HC 32

// ---------------- device scratch (allocation-free rule: static globals) ----
__device__ float g_agg[NN * DIM];   // (1+eps)*x + sum relu(x[src]+ea)
__device__ float g_tmp[NN * DIM];   // relu(agg@W1+b1)
__device__ float g_h[NN * DIM];     // LN(relu(.@W2+b2)) + x
__device__ float g_xp[NN * DIM];    // h @ gat_w
__device__ float g_out[NN * DIM];   // GAT weighted aggregation
__device__ float g_asrc[NN * HEADS];
__device__ float g_adst[NN * HEADS];
__device__ float g_wsum[NN * HEADS];

// ---------------- helpers ----------------
__device__ __forceinline__ float4 relu4(float4 v) {
    v.x = fmaxf(v.x, 0.f); v.y = fmaxf(v.y, 0.f);
    v.z = fmaxf(v.z, 0.f); v.w = fmaxf(v.w, 0.f);
    return v;
}

__device__ __forceinline__ void red_add_v4(float* p, float4 v) {
    asm volatile("red.global.add.v4.f32 [%0], {%1,%2,%3,%4};"
                 :: "l"(p), "f"(v.x), "f"(v.y), "f"(v.z), "f"(v.w) : "memory");
}

// ---------------- K1: agg init = (1+eps)*x ----------------
__global__ __launch_bounds__(256) void k_init_agg(const float* __restrict__ x,
                                                  const float* __restrict__ eps) {
    int i = blockIdx.x * 256 + threadIdx.x;        // float4 index, exactly N*DIM/4
    float e = 1.0f + eps[0];
    float4 v = ((const float4*)x)[i];
    v.x *= e; v.y *= e; v.z *= e; v.w *= e;
    ((float4*)g_agg)[i] = v;
}

// ---------------- K2: GINE edge pass (warp per edge) ----------------
__global__ __launch_bounds__(256) void k_gine_edge(const float* __restrict__ x,
                                                   const int* __restrict__ ei,
                                                   const float* __restrict__ ea) {
    int w = (blockIdx.x * 256 + threadIdx.x) >> 5;   // edge id
    int lane = threadIdx.x & 31;
    if (w >= EE) return;
    int s = ei[w];
    int d = ei[EE + w];
    float4 xv = __ldg(&((const float4*)x)[(size_t)s * 32 + lane]);
    float4 ev = __ldg(&((const float4*)ea)[(size_t)w * 32 + lane]);
    float4 m;
    m.x = fmaxf(xv.x + ev.x, 0.f);
    m.y = fmaxf(xv.y + ev.y, 0.f);
    m.z = fmaxf(xv.z + ev.z, 0.f);
    m.w = fmaxf(xv.w + ev.w, 0.f);
    red_add_v4(g_agg + (size_t)d * DIM + lane * 4, m);
}

// ---------------- K3: 128x128 SGEMM, 64-row tile, fused epilogues ----------
// EPI 0: out = relu(in@W + b)
// EPI 1: out = LN(relu(in@W + b); p0=g, p1=b) + p2(resid)
// EPI 2: out = in@W (xp); q0/q1 = per-head dot with p0=att_src / p1=att_dst
template <int EPI>
__global__ __launch_bounds__(256) void k_gemm128(
    const float* __restrict__ in, const float* __restrict__ W,
    const float* __restrict__ bias, float* __restrict__ out, int n,
    const float* __restrict__ p0, const float* __restrict__ p1,
    const float* __restrict__ p2, float* __restrict__ q0, float* __restrict__ q1) {
    extern __shared__ float smem[];
    float* Ws = smem;                 // 128*128
    float* Is = smem + DIM * DIM;     // 64*128
    float4* Ws4 = (float4*)Ws;
    float4* Is4 = (float4*)Is;

    const int t = threadIdx.x;
    const int row0 = blockIdx.x * 64;

    // stage W (16384 floats = 4096 float4)
    #pragma unroll
    for (int i = 0; i < 16; i++) Ws4[t + 256 * i] = ((const float4*)W)[t + 256 * i];
    // stage input tile (64 rows x 128 = 2048 float4)
    #pragma unroll
    for (int i = 0; i < 8; i++) {
        int idx = t + 256 * i;
        int r = idx >> 5;
        Is4[idx] = (row0 + r < n) ? ((const float4*)in)[(size_t)(row0 + r) * 32 + (idx & 31)]
                                  : make_float4(0.f, 0.f, 0.f, 0.f);
    }
    __syncthreads();

    const int tx = t & 31;    // column group (4 cols)
    const int ty = t >> 5;    // row group (8 rows)
    float acc[8][4];
    float4 bv = bias ? ((const float4*)bias)[tx] : make_float4(0.f, 0.f, 0.f, 0.f);
    #pragma unroll
    for (int r = 0; r < 8; r++) {
        acc[r][0] = bv.x; acc[r][1] = bv.y; acc[r][2] = bv.z; acc[r][3] = bv.w;
    }

    #pragma unroll 4
    for (int k = 0; k < DIM; k++) {
        float4 w4 = Ws4[k * 32 + tx];
        #pragma unroll
        for (int r = 0; r < 8; r++) {
            float a = Is[(ty * 8 + r) * DIM + k];
            acc[r][0] = fmaf(a, w4.x, acc[r][0]);
            acc[r][1] = fmaf(a, w4.y, acc[r][1]);
            acc[r][2] = fmaf(a, w4.z, acc[r][2]);
            acc[r][3] = fmaf(a, w4.w, acc[r][3]);
        }
    }

    if (EPI == 0) {
        #pragma unroll
        for (int r = 0; r < 8; r++) {
            int row = row0 + ty * 8 + r;
            if (row < n) {
                float4 v = make_float4(acc[r][0], acc[r][1], acc[r][2], acc[r][3]);
                ((float4*)out)[(size_t)row * 32 + tx] = relu4(v);
            }
        }
        return;
    }

    // write result tile back to shared for row-wise epilogues
    __syncthreads();
    #pragma unroll
    for (int r = 0; r < 8; r++)
        Is4[(ty * 8 + r) * 32 + tx] = make_float4(acc[r][0], acc[r][1], acc[r][2], acc[r][3]);
    __syncthreads();

    const int lane = t & 31;
    const int wid = t >> 5;
    #pragma unroll
    for (int rr = 0; rr < 8; rr++) {
        int r = wid * 8 + rr;
        int row = row0 + r;
        if (row >= n) break;
        float4 v = Is4[r * 32 + lane];

        if (EPI == 1) {
            v = relu4(v);
            float s = v.x + v.y + v.z + v.w;
            #pragma unroll
            for (int o = 16; o; o >>= 1) s += __shfl_xor_sync(0xffffffffu, s, o);
            float mu = s * (1.0f / DIM);
            float dx = v.x - mu, dy = v.y - mu, dz = v.z - mu, dw = v.w - mu;
            float ss = dx * dx + dy * dy + dz * dz + dw * dw;
            #pragma unroll
            for (int o = 16; o; o >>= 1) ss += __shfl_xor_sync(0xffffffffu, ss, o);
            float inv = rsqrtf(ss * (1.0f / DIM) + 1e-5f);
            float4 g = ((const float4*)p0)[lane];
            float4 b = ((const float4*)p1)[lane];
            float4 res = ((const float4*)p2)[(size_t)row * 32 + lane];
            float4 o4;
            o4.x = dx * inv * g.x + b.x + res.x;
            o4.y = dy * inv * g.y + b.y + res.y;
            o4.z = dz * inv * g.z + b.z + res.z;
            o4.w = dw * inv * g.w + b.w + res.w;
            ((float4*)out)[(size_t)row * 32 + lane] = o4;
        } else {  // EPI == 2: xp + attention coefficients
            ((float4*)out)[(size_t)row * 32 + lane] = v;
            float4 as = ((const float4*)p0)[lane];   // att_src flat [128]
            float4 ad = ((const float4*)p1)[lane];   // att_dst flat [128]
            float ps = v.x * as.x + v.y * as.y + v.z * as.z + v.w * as.w;
            float pd = v.x * ad.x + v.y * ad.y + v.z * ad.z + v.w * ad.w;
            #pragma unroll
            for (int o = 4; o; o >>= 1) {
                ps += __shfl_down_sync(0xffffffffu, ps, o, 8);
                pd += __shfl_down_sync(0xffffffffu, pd, o, 8);
            }
            if ((lane & 7) == 0) {
                q0[row * HEADS + (lane >> 3)] = ps;
                q1[row * HEADS + (lane >> 3)] = pd;
            }
        }
    }
}

// ---------------- K4: GAT self-loop init (warp per node) ----------------
__global__ __launch_bounds__(256) void k_gat_init() {
    int node = (blockIdx.x * 256 + threadIdx.x) >> 5;
    int lane = threadIdx.x & 31;
    if (node >= NN) return;
    float aw = 0.f;
    if (lane < HEADS) {
        float l = g_asrc[node * HEADS + lane] + g_adst[node * HEADS + lane];
        l = (l > 0.f) ? l : 0.2f * l;
        aw = expf(l);
        g_wsum[node * HEADS + lane] = aw;
    }
    float w = __shfl_sync(0xffffffffu, aw, lane >> 3);
    float4 v = ((const float4*)g_xp)[(size_t)node * 32 + lane];
    ((float4*)g_out)[(size_t)node * 32 + lane] =
        make_float4(w * v.x, w * v.y, w * v.z, w * v.w);
}

// ---------------- K5: GAT edge pass (warp per edge, fused softmax-sum+agg) --
__global__ __launch_bounds__(256) void k_gat_edge(const int* __restrict__ ei) {
    int e = (blockIdx.x * 256 + threadIdx.x) >> 5;
    int lane = threadIdx.x & 31;
    if (e >= EE) return;
    int s = ei[e];
    int d = ei[EE + e];
    float aw = 0.f;
    if (lane < HEADS) {
        float l = g_asrc[s * HEADS + lane] + g_adst[d * HEADS + lane];
        l = (l > 0.f) ? l : 0.2f * l;
        aw = expf(l);
        atomicAdd(&g_wsum[d * HEADS + lane], aw);
    }
    float w = __shfl_sync(0xffffffffu, aw, lane >> 3);
    float4 v = __ldg(&((const float4*)g_xp)[(size_t)s * 32 + lane]);
    red_add_v4(g_out + (size_t)d * DIM + lane * 4,
               make_float4(w * v.x, w * v.y, w * v.z, w * v.w));
}

// ---------------- K6: final epilogue (warp per node) ----------------
__global__ __launch_bounds__(256) void k_final(const float* __restrict__ gat_b,
                                               const float* __restrict__ ln2_g,
                                               const float* __restrict__ ln2_b,
                                               float* __restrict__ outp) {
    int node = (blockIdx.x * 256 + threadIdx.x) >> 5;
    int lane = threadIdx.x & 31;
    if (node >= NN) return;
    float4 v = ((const float4*)g_out)[(size_t)node * 32 + lane];
    float ws = g_wsum[node * HEADS + (lane >> 3)] + 1e-16f;
    float inv_s = 1.0f / ws;
    float4 gb = ((const float4*)gat_b)[lane];
    v.x = fmaxf(v.x * inv_s + gb.x, 0.f);
    v.y = fmaxf(v.y * inv_s + gb.y, 0.f);
    v.z = fmaxf(v.z * inv_s + gb.z, 0.f);
    v.w = fmaxf(v.w * inv_s + gb.w, 0.f);
    float s = v.x + v.y + v.z + v.w;
    #pragma unroll
    for (int o = 16; o; o >>= 1) s += __shfl_xor_sync(0xffffffffu, s, o);
    float mu = s * (1.0f / DIM);
    float dx = v.x - mu, dy = v.y - mu, dz = v.z - mu, dw = v.w - mu;
    float ss = dx * dx + dy * dy + dz * dz + dw * dw;
    #pragma unroll
    for (int o = 16; o; o >>= 1) ss += __shfl_xor_sync(0xffffffffu, ss, o);
    float inv = rsqrtf(ss * (1.0f / DIM) + 1e-5f);
    float4 g = ((const float4*)ln2_g)[lane];
    float4 b = ((const float4*)ln2_b)[lane];
    float4 h = ((const float4*)g_h)[(size_t)node * 32 + lane];
    float4 o4;
    o4.x = dx * inv * g.x + b.x + h.x;
    o4.y = dy * inv * g.y + b.y + h.y;
    o4.z = dz * inv * g.z + b.z + h.z;
    o4.w = dw * inv * g.w + b.w + h.w;
    ((float4*)outp)[(size_t)node * 32 + lane] = o4;
}

// ---------------- launch ----------------
extern "C" void kernel_launch(void* const* d_in, const int* in_sizes, int n_in,
                              void* d_out, int out_size) {
    const float* x      = (const float*)d_in[0];
    const int*   ei     = (const int*)d_in[1];
    const float* ea     = (const float*)d_in[2];
    const float* eps    = (const float*)d_in[3];
    const float* w1     = (const float*)d_in[4];
    const float* b1     = (const float*)d_in[5];
    const float* w2     = (const float*)d_in[6];
    const float* b2     = (const float*)d_in[7];
    const float* ln1_g  = (const float*)d_in[8];
    const float* ln1_b  = (const float*)d_in[9];
    const float* gat_w  = (const float*)d_in[10];
    const float* att_s  = (const float*)d_in[11];
    const float* att_d  = (const float*)d_in[12];
    const float* gat_b  = (const float*)d_in[13];
    const float* ln2_g  = (const float*)d_in[14];
    const float* ln2_b  = (const float*)d_in[15];
    float* outp = (float*)d_out;

    const int smem = (DIM * DIM + 64 * DIM) * (int)sizeof(float);  // 96 KB
    cudaFuncSetAttribute(k_gemm128<0>, cudaFuncAttributeMaxDynamicSharedMemorySize, smem);
    cudaFuncSetAttribute(k_gemm128<1>, cudaFuncAttributeMaxDynamicSharedMemorySize, smem);
    cudaFuncSetAttribute(k_gemm128<2>, cudaFuncAttributeMaxDynamicSharedMemorySize, smem);

    float* agg = nullptr; cudaGetSymbolAddress((void**)&agg, g_agg);
    float* tmp = nullptr; cudaGetSymbolAddress((void**)&tmp, g_tmp);
    float* h   = nullptr; cudaGetSymbolAddress((void**)&h, g_h);
    float* xp  = nullptr; cudaGetSymbolAddress((void**)&xp, g_xp);
    float* asrc= nullptr; cudaGetSymbolAddress((void**)&asrc, g_asrc);
    float* adst= nullptr; cudaGetSymbolAddress((void**)&adst, g_adst);

    const int edge_blocks = EE / 8;               // 200000 (warp per edge)
    const int node_blocks = (NN + 7) / 8;         // 12500  (warp per node)
    const int vec_blocks  = (NN * DIM / 4) / 256; // 12500

    k_init_agg<<<vec_blocks, 256>>>(x, eps);
    k_gine_edge<<<edge_blocks, 256>>>(x, ei, ea);

    const int gblocks = (NN + 63) / 64;
    k_gemm128<0><<<gblocks, 256, smem>>>(agg, w1, b1, tmp, NN,
                                         nullptr, nullptr, nullptr, nullptr, nullptr);
    k_gemm128<1><<<gblocks, 256, smem>>>(tmp, w2, b2, h, NN,
                                         ln1_g, ln1_b, x, nullptr, nullptr);
    k_gemm128<2><<<gblocks, 256, smem>>>(h, gat_w, nullptr, xp, NN,
                                         att_s, att_d, nullptr, asrc, adst);

    k_gat_init<<<node_blocks, 256>>>();
    k_gat_edge<<<edge_blocks, 256>>>(ei);
    k_final<<<node_blocks, 256>>>(gat_b, ln2_g, ln2_b, outp);
}

// round 3
// speedup vs baseline: 1.0135x; 1.0135x over previous
#include <cuda_runtime.h>
#include <cuda_bf16.h>
#include <math.h>

#define NN 100000
#define EE 1600000
#define DIM 128
#define HEADS 4
#define HC 32

// ---------------- device scratch (allocation-free rule: static globals) ----
__device__ float g_agg[NN * DIM];   // (1+eps)*x + sum relu(x[src]+ea)
__device__ float g_tmp[NN * DIM];   // relu(agg@W1+b1)
__device__ float g_h[NN * DIM];     // LN(relu(.@W2+b2)) + x
__device__ float g_xp[NN * DIM];    // h @ gat_w
__device__ float g_out[NN * DIM];   // GAT weighted aggregation
__device__ float g_asrc[NN * HEADS];
__device__ float g_adst[NN * HEADS];
__device__ float g_wsum[NN * HEADS];

// ---------------- helpers ----------------
__device__ __forceinline__ float4 relu4(float4 v) {
    v.x = fmaxf(v.x, 0.f); v.y = fmaxf(v.y, 0.f);
    v.z = fmaxf(v.z, 0.f); v.w = fmaxf(v.w, 0.f);
    return v;
}

__device__ __forceinline__ void red_add_v4(float* p, float4 v) {
    asm volatile("red.global.add.v4.f32 [%0], {%1,%2,%3,%4};"
                 :: "l"(p), "f"(v.x), "f"(v.y), "f"(v.z), "f"(v.w) : "memory");
}

// ---------------- K1: agg init = (1+eps)*x ----------------
__global__ __launch_bounds__(256) void k_init_agg(const float* __restrict__ x,
                                                  const float* __restrict__ eps) {
    int i = blockIdx.x * 256 + threadIdx.x;        // float4 index, exactly N*DIM/4
    float e = 1.0f + eps[0];
    float4 v = ((const float4*)x)[i];
    v.x *= e; v.y *= e; v.z *= e; v.w *= e;
    ((float4*)g_agg)[i] = v;
}

// ---------------- K2: GINE edge pass (warp per edge) ----------------
__global__ __launch_bounds__(256) void k_gine_edge(const float* __restrict__ x,
                                                   const int* __restrict__ ei,
                                                   const float* __restrict__ ea) {
    int w = (blockIdx.x * 256 + threadIdx.x) >> 5;   // edge id
    int lane = threadIdx.x & 31;
    if (w >= EE) return;
    int s = ei[w];
    int d = ei[EE + w];
    float4 xv = __ldg(&((const float4*)x)[(size_t)s * 32 + lane]);
    float4 ev = __ldg(&((const float4*)ea)[(size_t)w * 32 + lane]);
    float4 m;
    m.x = fmaxf(xv.x + ev.x, 0.f);
    m.y = fmaxf(xv.y + ev.y, 0.f);
    m.z = fmaxf(xv.z + ev.z, 0.f);
    m.w = fmaxf(xv.w + ev.w, 0.f);
    red_add_v4(g_agg + (size_t)d * DIM + lane * 4, m);
}

// ---------------- K3: 128x128 SGEMM, 64-row tile, fused epilogues ----------
// EPI 0: out = relu(in@W + b)
// EPI 1: out = LN(relu(in@W + b); p0=g, p1=b) + p2(resid)
// EPI 2: out = in@W (xp); q0/q1 = per-head dot with p0=att_src / p1=att_dst
template <int EPI>
__global__ __launch_bounds__(256) void k_gemm128(
    const float* __restrict__ in, const float* __restrict__ W,
    const float* __restrict__ bias, float* __restrict__ out, int n,
    const float* __restrict__ p0, const float* __restrict__ p1,
    const float* __restrict__ p2, float* __restrict__ q0, float* __restrict__ q1) {
    extern __shared__ float smem[];
    float* Ws = smem;                 // 128*128
    float* Is = smem + DIM * DIM;     // 64*128
    float4* Ws4 = (float4*)Ws;
    float4* Is4 = (float4*)Is;

    const int t = threadIdx.x;
    const int row0 = blockIdx.x * 64;

    // stage W (16384 floats = 4096 float4)
    #pragma unroll
    for (int i = 0; i < 16; i++) Ws4[t + 256 * i] = ((const float4*)W)[t + 256 * i];
    // stage input tile (64 rows x 128 = 2048 float4)
    #pragma unroll
    for (int i = 0; i < 8; i++) {
        int idx = t + 256 * i;
        int r = idx >> 5;
        Is4[idx] = (row0 + r < n) ? ((const float4*)in)[(size_t)(row0 + r) * 32 + (idx & 31)]
                                  : make_float4(0.f, 0.f, 0.f, 0.f);
    }
    __syncthreads();

    const int tx = t & 31;    // column group (4 cols)
    const int ty = t >> 5;    // row group (8 rows)
    float acc[8][4];
    float4 bv = bias ? ((const float4*)bias)[tx] : make_float4(0.f, 0.f, 0.f, 0.f);
    #pragma unroll
    for (int r = 0; r < 8; r++) {
        acc[r][0] = bv.x; acc[r][1] = bv.y; acc[r][2] = bv.z; acc[r][3] = bv.w;
    }

    #pragma unroll 4
    for (int k = 0; k < DIM; k++) {
        float4 w4 = Ws4[k * 32 + tx];
        #pragma unroll
        for (int r = 0; r < 8; r++) {
            float a = Is[(ty * 8 + r) * DIM + k];
            acc[r][0] = fmaf(a, w4.x, acc[r][0]);
            acc[r][1] = fmaf(a, w4.y, acc[r][1]);
            acc[r][2] = fmaf(a, w4.z, acc[r][2]);
            acc[r][3] = fmaf(a, w4.w, acc[r][3]);
        }
    }

    if (EPI == 0) {
        #pragma unroll
        for (int r = 0; r < 8; r++) {
            int row = row0 + ty * 8 + r;
            if (row < n) {
                float4 v = make_float4(acc[r][0], acc[r][1], acc[r][2], acc[r][3]);
                ((float4*)out)[(size_t)row * 32 + tx] = relu4(v);
            }
        }
        return;
    }

    // write result tile back to shared for row-wise epilogues
    __syncthreads();
    #pragma unroll
    for (int r = 0; r < 8; r++)
        Is4[(ty * 8 + r) * 32 + tx] = make_float4(acc[r][0], acc[r][1], acc[r][2], acc[r][3]);
    __syncthreads();

    const int lane = t & 31;
    const int wid = t >> 5;
    #pragma unroll
    for (int rr = 0; rr < 8; rr++) {
        int r = wid * 8 + rr;
        int row = row0 + r;
        if (row >= n) break;
        float4 v = Is4[r * 32 + lane];

        if (EPI == 1) {
            v = relu4(v);
            float s = v.x + v.y + v.z + v.w;
            #pragma unroll
            for (int o = 16; o; o >>= 1) s += __shfl_xor_sync(0xffffffffu, s, o);
            float mu = s * (1.0f / DIM);
            float dx = v.x - mu, dy = v.y - mu, dz = v.z - mu, dw = v.w - mu;
            float ss = dx * dx + dy * dy + dz * dz + dw * dw;
            #pragma unroll
            for (int o = 16; o; o >>= 1) ss += __shfl_xor_sync(0xffffffffu, ss, o);
            float inv = rsqrtf(ss * (1.0f / DIM) + 1e-5f);
            float4 g = ((const float4*)p0)[lane];
            float4 b = ((const float4*)p1)[lane];
            float4 res = ((const float4*)p2)[(size_t)row * 32 + lane];
            float4 o4;
            o4.x = dx * inv * g.x + b.x + res.x;
            o4.y = dy * inv * g.y + b.y + res.y;
            o4.z = dz * inv * g.z + b.z + res.z;
            o4.w = dw * inv * g.w + b.w + res.w;
            ((float4*)out)[(size_t)row * 32 + lane] = o4;
        } else {  // EPI == 2: xp + attention coefficients
            ((float4*)out)[(size_t)row * 32 + lane] = v;
            float4 as = ((const float4*)p0)[lane];   // att_src flat [128]
            float4 ad = ((const float4*)p1)[lane];   // att_dst flat [128]
            float ps = v.x * as.x + v.y * as.y + v.z * as.z + v.w * as.w;
            float pd = v.x * ad.x + v.y * ad.y + v.z * ad.z + v.w * ad.w;
            #pragma unroll
            for (int o = 4; o; o >>= 1) {
                ps += __shfl_down_sync(0xffffffffu, ps, o, 8);
                pd += __shfl_down_sync(0xffffffffu, pd, o, 8);
            }
            if ((lane & 7) == 0) {
                q0[row * HEADS + (lane >> 3)] = ps;
                q1[row * HEADS + (lane >> 3)] = pd;
            }
        }
    }
}

// ---------------- K4: GAT self-loop init (warp per node) ----------------
__global__ __launch_bounds__(256) void k_gat_init() {
    int node = (blockIdx.x * 256 + threadIdx.x) >> 5;
    int lane = threadIdx.x & 31;
    if (node >= NN) return;
    float aw = 0.f;
    if (lane < HEADS) {
        float l = g_asrc[node * HEADS + lane] + g_adst[node * HEADS + lane];
        l = (l > 0.f) ? l : 0.2f * l;
        aw = expf(l);
        g_wsum[node * HEADS + lane] = aw;
    }
    float w = __shfl_sync(0xffffffffu, aw, lane >> 3);
    float4 v = ((const float4*)g_xp)[(size_t)node * 32 + lane];
    ((float4*)g_out)[(size_t)node * 32 + lane] =
        make_float4(w * v.x, w * v.y, w * v.z, w * v.w);
}

// ---------------- K5: GAT edge pass (warp per edge, fused softmax-sum+agg) --
__global__ __launch_bounds__(256) void k_gat_edge(const int* __restrict__ ei) {
    int e = (blockIdx.x * 256 + threadIdx.x) >> 5;
    int lane = threadIdx.x & 31;
    if (e >= EE) return;
    int s = ei[e];
    int d = ei[EE + e];
    float aw = 0.f;
    if (lane < HEADS) {
        float l = g_asrc[s * HEADS + lane] + g_adst[d * HEADS + lane];
        l = (l > 0.f) ? l : 0.2f * l;
        aw = expf(l);
        atomicAdd(&g_wsum[d * HEADS + lane], aw);
    }
    float w = __shfl_sync(0xffffffffu, aw, lane >> 3);
    float4 v = __ldg(&((const float4*)g_xp)[(size_t)s * 32 + lane]);
    red_add_v4(g_out + (size_t)d * DIM + lane * 4,
               make_float4(w * v.x, w * v.y, w * v.z, w * v.w));
}

// ---------------- K6: final epilogue (warp per node) ----------------
__global__ __launch_bounds__(256) void k_final(const float* __restrict__ gat_b,
                                               const float* __restrict__ ln2_g,
                                               const float* __restrict__ ln2_b,
                                               float* __restrict__ outp) {
    int node = (blockIdx.x * 256 + threadIdx.x) >> 5;
    int lane = threadIdx.x & 31;
    if (node >= NN) return;
    float4 v = ((const float4*)g_out)[(size_t)node * 32 + lane];
    float ws = g_wsum[node * HEADS + (lane >> 3)] + 1e-16f;
    float inv_s = 1.0f / ws;
    float4 gb = ((const float4*)gat_b)[lane];
    v.x = fmaxf(v.x * inv_s + gb.x, 0.f);
    v.y = fmaxf(v.y * inv_s + gb.y, 0.f);
    v.z = fmaxf(v.z * inv_s + gb.z, 0.f);
    v.w = fmaxf(v.w * inv_s + gb.w, 0.f);
    float s = v.x + v.y + v.z + v.w;
    #pragma unroll
    for (int o = 16; o; o >>= 1) s += __shfl_xor_sync(0xffffffffu, s, o);
    float mu = s * (1.0f / DIM);
    float dx = v.x - mu, dy = v.y - mu, dz = v.z - mu, dw = v.w - mu;
    float ss = dx * dx + dy * dy + dz * dz + dw * dw;
    #pragma unroll
    for (int o = 16; o; o >>= 1) ss += __shfl_xor_sync(0xffffffffu, ss, o);
    float inv = rsqrtf(ss * (1.0f / DIM) + 1e-5f);
    float4 g = ((const float4*)ln2_g)[lane];
    float4 b = ((const float4*)ln2_b)[lane];
    float4 h = ((const float4*)g_h)[(size_t)node * 32 + lane];
    float4 o4;
    o4.x = dx * inv * g.x + b.x + h.x;
    o4.y = dy * inv * g.y + b.y + h.y;
    o4.z = dz * inv * g.z + b.z + h.z;
    o4.w = dw * inv * g.w + b.w + h.w;
    ((float4*)outp)[(size_t)node * 32 + lane] = o4;
}

// ---------------- launch ----------------
extern "C" void kernel_launch(void* const* d_in, const int* in_sizes, int n_in,
                              void* d_out, int out_size) {
    const float* x      = (const float*)d_in[0];
    const int*   ei     = (const int*)d_in[1];
    const float* ea     = (const float*)d_in[2];
    const float* eps    = (const float*)d_in[3];
    const float* w1     = (const float*)d_in[4];
    const float* b1     = (const float*)d_in[5];
    const float* w2     = (const float*)d_in[6];
    const float* b2     = (const float*)d_in[7];
    const float* ln1_g  = (const float*)d_in[8];
    const float* ln1_b  = (const float*)d_in[9];
    const float* gat_w  = (const float*)d_in[10];
    const float* att_s  = (const float*)d_in[11];
    const float* att_d  = (const float*)d_in[12];
    const float* gat_b  = (const float*)d_in[13];
    const float* ln2_g  = (const float*)d_in[14];
    const float* ln2_b  = (const float*)d_in[15];
    float* outp = (float*)d_out;

    const int smem = (DIM * DIM + 64 * DIM) * (int)sizeof(float);  // 96 KB
    cudaFuncSetAttribute(k_gemm128<0>, cudaFuncAttributeMaxDynamicSharedMemorySize, smem);
    cudaFuncSetAttribute(k_gemm128<1>, cudaFuncAttributeMaxDynamicSharedMemorySize, smem);
    cudaFuncSetAttribute(k_gemm128<2>, cudaFuncAttributeMaxDynamicSharedMemorySize, smem);

    float* agg = nullptr; cudaGetSymbolAddress((void**)&agg, g_agg);
    float* tmp = nullptr; cudaGetSymbolAddress((void**)&tmp, g_tmp);
    float* h   = nullptr; cudaGetSymbolAddress((void**)&h, g_h);
    float* xp  = nullptr; cudaGetSymbolAddress((void**)&xp, g_xp);
    float* asrc= nullptr; cudaGetSymbolAddress((void**)&asrc, g_asrc);
    float* adst= nullptr; cudaGetSymbolAddress((void**)&adst, g_adst);

    const int edge_blocks = EE / 8;               // 200000 (warp per edge)
    const int node_blocks = (NN + 7) / 8;         // 12500  (warp per node)
    const int vec_blocks  = (NN * DIM / 4) / 256; // 12500

    k_init_agg<<<vec_blocks, 256>>>(x, eps);
    k_gine_edge<<<edge_blocks, 256>>>(x, ei, ea);

    const int gblocks = (NN + 63) / 64;
    k_gemm128<0><<<gblocks, 256, smem>>>(agg, w1, b1, tmp, NN,
                                         nullptr, nullptr, nullptr, nullptr, nullptr);
    k_gemm128<1><<<gblocks, 256, smem>>>(tmp, w2, b2, h, NN,
                                         ln1_g, ln1_b, x, nullptr, nullptr);
    k_gemm128<2><<<gblocks, 256, smem>>>(h, gat_w, nullptr, xp, NN,
                                         att_s, att_d, nullptr, asrc, adst);

    k_gat_init<<<node_blocks, 256>>>();
    k_gat_edge<<<edge_blocks, 256>>>(ei);
    k_final<<<node_blocks, 256>>>(gat_b, ln2_g, ln2_b, outp);
}